// round 10
// baseline (speedup 1.0000x reference)
#include <cuda_runtime.h>
#include <cuda_fp16.h>
#include <cstdint>

#define QSC 0.36067376022224085f   // 0.25 * log2(e)

__device__ __forceinline__ uint32_t s2u(const void* p) {
    uint32_t a;
    asm("{ .reg .u64 t; cvta.to.shared.u64 t, %1; cvt.u32.u64 %0, t; }" : "=r"(a) : "l"(p));
    return a;
}
__device__ __forceinline__ uint32_t pkh2(float hi, float lo) {
    uint32_t d;
    asm("cvt.rn.f16x2.f32 %0, %1, %2;" : "=r"(d) : "f"(hi), "f"(lo));
    return d;
}
__device__ __forceinline__ uint32_t ex2h2(uint32_t x) {
    uint32_t d;
    asm("ex2.approx.f16x2 %0, %1;" : "=r"(d) : "r"(x));
    return d;
}
__device__ __forceinline__ uint32_t haddh2(uint32_t a, uint32_t b) {
    uint32_t d;
    asm("add.rn.f16x2 %0, %1, %2;" : "=r"(d) : "r"(a), "r"(b));
    return d;
}
__device__ __forceinline__ float hsumh2(uint32_t v) {
    float lo, hi;
    asm("{ .reg .b16 l, h; mov.b32 {l, h}, %2; cvt.f32.f16 %0, l; cvt.f32.f16 %1, h; }"
        : "=f"(lo), "=f"(hi) : "r"(v));
    return lo + hi;
}
#define LDSM4(r0, r1, r2, r3, a) \
    asm volatile("ldmatrix.sync.aligned.m8n8.x4.shared.b16 {%0,%1,%2,%3}, [%4];" \
        : "=r"(r0), "=r"(r1), "=r"(r2), "=r"(r3) : "r"(a))
#define MMA_F16(c, a, b0, b1) \
    asm volatile("mma.sync.aligned.m16n8k16.row.col.f32.f16.f16.f32 " \
        "{%0,%1,%2,%3},{%4,%5,%6,%7},{%8,%9},{%0,%1,%2,%3};" \
        : "+f"((c)[0]), "+f"((c)[1]), "+f"((c)[2]), "+f"((c)[3]) \
        : "r"((a)[0]), "r"((a)[1]), "r"((a)[2]), "r"((a)[3]), "r"(b0), "r"(b1))
#define MMA_F16C(c, a, b0, b1) \
    asm volatile("mma.sync.aligned.m16n8k16.row.col.f16.f16.f16.f16 " \
        "{%0,%1},{%2,%3,%4,%5},{%6,%7},{%0,%1};" \
        : "+r"((c)[0]), "+r"((c)[1]) \
        : "r"((a)[0]), "r"((a)[1]), "r"((a)[2]), "r"((a)[3]), "r"(b0), "r"(b1))

// CTA = one (window, head): 512 q x 512 k, 512 threads, 16 warps.
// warp w: query group qg = w>>1 (64 queries), key split ks = w&1 (256 keys).
// smem (dynamic, 86016 B):
//  mainloop: Ks @ 0 (512 x 48B = 24576), Vh @ 24576 (16 dims x 1024B = 16384)
//  after:    Po0 @ 0 (512 x 80B), Po1 @ 40960 (512 x 80B), Rs @ 81920 (512 x 8B)
#define VH_OFF 24576
#define PO1_OFF 40960
#define RS_OFF 81920

extern "C" __global__ void __launch_bounds__(512, 1)
cssa_mma(const float* __restrict__ qkv, const float* __restrict__ wconv,
         const float* __restrict__ bconv, float* __restrict__ out)
{
    extern __shared__ char sm[];
    char* Ks = sm;
    char* Vh = sm + VH_OFF;
    char* Po0 = sm;
    char* Po1 = sm + PO1_OFF;
    char* Rs = sm + RS_OFF;
    __shared__ float wc[16][9];
    __shared__ float bc[16];

    const int blk = blockIdx.x;
    const int h = blk & 3, wi = blk >> 2, b = wi >> 3, wx = wi & 7;
    const int tid = threadIdx.x, lane = tid & 31, w = tid >> 5;
    const int qg = w >> 1, ks = w & 1;

    const size_t bs = (size_t)4096 * 64;
    const float* qb = qkv + (size_t)b * bs + h * 16;
    const float* kb = qb + (size_t)32 * bs;
    const float* vb = kb + (size_t)32 * bs;

    if (tid < 144) wc[tid / 9][tid % 9] = wconv[(h * 16 + tid / 9) * 9 + tid % 9];
    if (tid < 16)  bc[tid] = bconv[h * 16 + tid];

    // ---------------- staging: one token per thread ----------------
    {
        const int t = tid;
        const int n = ((t >> 3) << 6) + (wx << 3) + (t & 7);
        const float4* kr = (const float4*)(kb + (size_t)n * 64);
        const float4* vr = (const float4*)(vb + (size_t)n * 64);
        uint32_t kh[8];
        #pragma unroll
        for (int c = 0; c < 4; c++) {
            const float4 k4 = kr[c];
            kh[c * 2 + 0] = pkh2(k4.y, k4.x);
            kh[c * 2 + 1] = pkh2(k4.w, k4.z);
            const float4 v4 = vr[c];
            const float e[4] = {v4.x, v4.y, v4.z, v4.w};
            #pragma unroll
            for (int jj = 0; jj < 4; jj++) {
                const int d = c * 4 + jj;
                *(__half*)(Vh + d * 1024 + (((t >> 3) ^ (d & 7)) << 4) + ((t & 7) << 1)) =
                    __float2half_rn(e[jj]);
            }
        }
        *(uint4*)(Ks + t * 48)      = make_uint4(kh[0], kh[1], kh[2], kh[3]);
        *(uint4*)(Ks + t * 48 + 16) = make_uint4(kh[4], kh[5], kh[6], kh[7]);
    }

    // ---------------- Q A-fragments direct from gmem (4 mt tiles) ----------------
    uint32_t qf[4][4];
    {
        const int g  = lane >> 2;
        const int t2 = (lane & 3) * 2;
        #pragma unroll
        for (int mt = 0; mt < 4; mt++) {
            const int r0 = qg * 64 + mt * 16 + g;
            #pragma unroll
            for (int half8 = 0; half8 < 2; half8++) {
                const int rq = r0 + half8 * 8;
                const int n  = ((rq >> 3) << 6) + (wx << 3) + (rq & 7);
                const float2 f0 = *(const float2*)(qb + (size_t)n * 64 + t2);
                const float2 f1 = *(const float2*)(qb + (size_t)n * 64 + 8 + t2);
                qf[mt][half8]     = pkh2(f0.y * QSC, f0.x * QSC);
                qf[mt][half8 + 2] = pkh2(f1.y * QSC, f1.x * QSC);
            }
        }
    }
    __syncthreads();

    // ---------------- main loop: 256 keys (this warp's split) ----------------
    const uint32_t aK = s2u(Ks), aV = s2u(Vh);
    const int krow = (lane & 7) + ((lane >> 4) & 1) * 8;
    const int kseg = (lane >> 3) & 1;
    const uint32_t aKl = aK + krow * 48 + kseg * 16 + ks * 16 * 768;

    const int vd = ((lane >> 4) & 1) * 8 + (lane & 7);
    const uint32_t aVd = aV + vd * 1024;
    const int vsw = (vd & 7) << 4;
    const int vm = ((lane >> 3) & 1) << 4;
    const int vbase = ks * 512;              // byte offset for key split

    float O[4][2][4] = {};                   // [mt][dims0-7 | dims8-15]
    float rs[8] = {0.f};                     // [mt][row g | row g+8]

    #pragma unroll 2
    for (int nb = 0; nb < 16; nb++) {
        uint32_t kf[4], vf[4];
        LDSM4(kf[0], kf[1], kf[2], kf[3], aKl + nb * 768);
        LDSM4(vf[0], vf[1], vf[2], vf[3], aVd + (uint32_t)((vbase + nb * 32 + vm) ^ vsw));

        #pragma unroll
        for (int mt = 0; mt < 4; mt++) {
            uint32_t s0[2] = {0u, 0u}, s1[2] = {0u, 0u};
            MMA_F16C(s0, qf[mt], kf[0], kf[1]);   // keys 0-7
            MMA_F16C(s1, qf[mt], kf[2], kf[3]);   // keys 8-15
            uint32_t A[4];
            A[0] = ex2h2(s0[0]);
            A[1] = ex2h2(s0[1]);
            A[2] = ex2h2(s1[0]);
            A[3] = ex2h2(s1[1]);
            rs[mt * 2 + 0] += hsumh2(haddh2(A[0], A[2]));
            rs[mt * 2 + 1] += hsumh2(haddh2(A[1], A[3]));
            MMA_F16(O[mt][0], A, vf[0], vf[1]);
            MMA_F16(O[mt][1], A, vf[2], vf[3]);
        }
    }

    // quad-reduce partial rowsums
    #pragma unroll
    for (int i = 0; i < 8; i++) {
        rs[i] += __shfl_xor_sync(0xFFFFFFFFu, rs[i], 1);
        rs[i] += __shfl_xor_sync(0xFFFFFFFFu, rs[i], 2);
    }

    __syncthreads();   // all warps done reading Ks/Vh (partials overlay them)

    // ---------------- write split-K partials ----------------
    char* Po = ks ? Po1 : Po0;
    #pragma unroll
    for (int mt = 0; mt < 4; mt++) {
        #pragma unroll
        for (int vt = 0; vt < 2; vt++) {
            const int r0 = qg * 64 + mt * 16 + (lane >> 2);
            const int cb = (vt * 8 + (lane & 3) * 2) * 4;
            *(float2*)(Po + r0 * 80 + cb)       = make_float2(O[mt][vt][0], O[mt][vt][1]);
            *(float2*)(Po + (r0 + 8) * 80 + cb) = make_float2(O[mt][vt][2], O[mt][vt][3]);
        }
        if ((lane & 3) == 0) {
            const int r0 = qg * 64 + mt * 16 + (lane >> 2);
            *(float*)(Rs + r0 * 8 + ks * 4)       = rs[mt * 2 + 0];
            *(float*)(Rs + (r0 + 8) * 8 + ks * 4) = rs[mt * 2 + 1];
        }
    }
    __syncthreads();

    // ---------------- epilogue: 1 query/thread; combine splits; LePE from gmem ----------------
    {
        const int t = tid, y = t >> 3, x = t & 7;
        const float2 srs = *(const float2*)(Rs + t * 8);
        const float inv = 1.0f / (srs.x + srs.y);
        float o[16];
        #pragma unroll
        for (int c = 0; c < 4; c++) {
            const float4 f0 = *(const float4*)(Po0 + t * 80 + c * 16);
            const float4 f1 = *(const float4*)(Po1 + t * 80 + c * 16);
            o[c * 4 + 0] = (f0.x + f1.x) * inv + bc[c * 4 + 0];
            o[c * 4 + 1] = (f0.y + f1.y) * inv + bc[c * 4 + 1];
            o[c * 4 + 2] = (f0.z + f1.z) * inv + bc[c * 4 + 2];
            o[c * 4 + 3] = (f0.w + f1.w) * inv + bc[c * 4 + 3];
        }

        #pragma unroll
        for (int dy = -1; dy <= 1; dy++) {
            const int yy = y + dy;
            if ((unsigned)yy >= 64u) continue;
            #pragma unroll
            for (int dx = -1; dx <= 1; dx++) {
                const int xx = x + dx;
                if ((unsigned)xx >= 8u) continue;
                const int nn = (yy << 6) + (wx << 3) + xx;
                const float4* vrow = (const float4*)(vb + (size_t)nn * 64);
                const int widx = (dy + 1) * 3 + (dx + 1);
                #pragma unroll
                for (int c = 0; c < 4; c++) {
                    const float4 v = vrow[c];
                    o[c * 4]     += wc[c * 4][widx] * v.x;
                    o[c * 4 + 1] += wc[c * 4 + 1][widx] * v.y;
                    o[c * 4 + 2] += wc[c * 4 + 2][widx] * v.z;
                    o[c * 4 + 3] += wc[c * 4 + 3][widx] * v.w;
                }
            }
        }
        const int n = (y << 6) + (wx << 3) + x;
        float4* dst = (float4*)(out + ((size_t)b * 4096 + n) * 64 + h * 16);
        #pragma unroll
        for (int c = 0; c < 4; c++)
            dst[c] = make_float4(o[c * 4], o[c * 4 + 1], o[c * 4 + 2], o[c * 4 + 3]);
    }
}

extern "C" void kernel_launch(void* const* d_in, const int* in_sizes, int n_in,
                              void* d_out, int out_size) {
    const float* qkv = (const float*)d_in[0];
    const float* wconv = (const float*)d_in[1];
    const float* bconv = (const float*)d_in[2];
    float* out = (float*)d_out;
    const int smem_bytes = 86016;
    cudaFuncSetAttribute(cssa_mma, cudaFuncAttributeMaxDynamicSharedMemorySize, smem_bytes);
    cssa_mma<<<1024, 512, smem_bytes>>>(qkv, wconv, bconv, out);
}

// round 11
// speedup vs baseline: 1.0143x; 1.0143x over previous
#include <cuda_runtime.h>
#include <cuda_fp16.h>
#include <cstdint>

#define QSC 0.36067376022224085f   // 0.25 * log2(e)

__device__ __forceinline__ uint32_t s2u(const void* p) {
    uint32_t a;
    asm("{ .reg .u64 t; cvta.to.shared.u64 t, %1; cvt.u32.u64 %0, t; }" : "=r"(a) : "l"(p));
    return a;
}
__device__ __forceinline__ uint32_t pkh2(float hi, float lo) {
    uint32_t d;
    asm("cvt.rn.f16x2.f32 %0, %1, %2;" : "=r"(d) : "f"(hi), "f"(lo));
    return d;
}
__device__ __forceinline__ uint32_t ex2h2(uint32_t x) {
    uint32_t d;
    asm("ex2.approx.f16x2 %0, %1;" : "=r"(d) : "r"(x));
    return d;
}
#define LDSM4(r0, r1, r2, r3, a) \
    asm volatile("ldmatrix.sync.aligned.m8n8.x4.shared.b16 {%0,%1,%2,%3}, [%4];" \
        : "=r"(r0), "=r"(r1), "=r"(r2), "=r"(r3) : "r"(a))
#define LDSM2(r0, r1, a) \
    asm volatile("ldmatrix.sync.aligned.m8n8.x2.shared.b16 {%0,%1}, [%2];" \
        : "=r"(r0), "=r"(r1) : "r"(a))
#define MMA_F16(c, a, b0, b1) \
    asm volatile("mma.sync.aligned.m16n8k16.row.col.f32.f16.f16.f32 " \
        "{%0,%1,%2,%3},{%4,%5,%6,%7},{%8,%9},{%0,%1,%2,%3};" \
        : "+f"((c)[0]), "+f"((c)[1]), "+f"((c)[2]), "+f"((c)[3]) \
        : "r"((a)[0]), "r"((a)[1]), "r"((a)[2]), "r"((a)[3]), "r"(b0), "r"(b1))
#define MMA_F16C(c, a, b0, b1) \
    asm volatile("mma.sync.aligned.m16n8k16.row.col.f16.f16.f16.f16 " \
        "{%0,%1},{%2,%3,%4,%5},{%6,%7},{%0,%1};" \
        : "+r"((c)[0]), "+r"((c)[1]) \
        : "r"((a)[0]), "r"((a)[1]), "r"((a)[2]), "r"((a)[3]), "r"(b0), "r"(b1))

// CTA = one (window, head): 512 q x 512 k, 512 threads, 16 warps, 32 q/warp.
// smem (dynamic, 73728 B):
//  Qs @ 0     : 512 rows x 48B stride, f16 [16 dims]             (24 KB)
//  Ks @ 24576 : same                                              (24 KB)
//  Vh @ 49152 : f16 transposed [24 dims][512 keys], swizzled;
//               dim16 = 1.0 (rowsum), dims17-23 = 0               (24 KB)
//  Os @ 0     : overlay on Qs/Ks after mainloop, 512 x 80B        (40 KB)

extern "C" __global__ void __launch_bounds__(512, 1)
cssa_mma(const float* __restrict__ qkv, const float* __restrict__ wconv,
         const float* __restrict__ bconv, float* __restrict__ out)
{
    extern __shared__ char sm[];
    char* Qs = sm;
    char* Ks = sm + 24576;
    char* Vh = sm + 49152;
    char* Os = sm;
    __shared__ float wc[16][9];
    __shared__ float bc[16];

    const int blk = blockIdx.x;
    const int h = blk & 3, wi = blk >> 2, b = wi >> 3, wx = wi & 7;
    const int tid = threadIdx.x, lane = tid & 31, w = tid >> 5;

    const size_t bs = (size_t)4096 * 64;
    const float* qb = qkv + (size_t)b * bs + h * 16;
    const float* kb = qb + (size_t)32 * bs;
    const float* vb = kb + (size_t)32 * bs;

    if (tid < 144) wc[tid / 9][tid % 9] = wconv[(h * 16 + tid / 9) * 9 + tid % 9];
    if (tid < 16)  bc[tid] = bconv[h * 16 + tid];

    // ---------------- staging: one token per thread ----------------
    {
        const int t = tid;
        const int n = ((t >> 3) << 6) + (wx << 3) + (t & 7);
        const float4* qr = (const float4*)(qb + (size_t)n * 64);
        const float4* kr = (const float4*)(kb + (size_t)n * 64);
        const float4* vr = (const float4*)(vb + (size_t)n * 64);
        uint32_t qh[8], kh[8];
        #pragma unroll
        for (int c = 0; c < 4; c++) {
            const float4 q4 = qr[c];
            qh[c * 2 + 0] = pkh2(q4.y * QSC, q4.x * QSC);
            qh[c * 2 + 1] = pkh2(q4.w * QSC, q4.z * QSC);
            const float4 k4 = kr[c];
            kh[c * 2 + 0] = pkh2(k4.y, k4.x);
            kh[c * 2 + 1] = pkh2(k4.w, k4.z);
            const float4 v4 = vr[c];
            const float e[4] = {v4.x, v4.y, v4.z, v4.w};
            #pragma unroll
            for (int jj = 0; jj < 4; jj++) {
                const int d = c * 4 + jj;
                *(__half*)(Vh + d * 1024 + (((t >> 3) ^ (d & 7)) << 4) + ((t & 7) << 1)) =
                    __float2half_rn(e[jj]);
            }
        }
        #pragma unroll
        for (int d = 16; d < 24; d++) {
            *(uint16_t*)(Vh + d * 1024 + (((t >> 3) ^ (d & 7)) << 4) + ((t & 7) << 1)) =
                (d == 16) ? (uint16_t)0x3C00u : (uint16_t)0u;
        }
        *(uint4*)(Qs + t * 48)      = make_uint4(qh[0], qh[1], qh[2], qh[3]);
        *(uint4*)(Qs + t * 48 + 16) = make_uint4(qh[4], qh[5], qh[6], qh[7]);
        *(uint4*)(Ks + t * 48)      = make_uint4(kh[0], kh[1], kh[2], kh[3]);
        *(uint4*)(Ks + t * 48 + 16) = make_uint4(kh[4], kh[5], kh[6], kh[7]);
    }
    __syncthreads();

    // ---------------- main loop: warp owns 32 queries (2 mt tiles) ----------------
    const int qbase = w * 32;
    const uint32_t aQ = s2u(Qs), aK = s2u(Ks), aV = s2u(Vh);

    const int qrow = (lane & 7) + ((lane >> 3) & 1) * 8;
    const int qseg = (lane >> 4) & 1;
    uint32_t qf[2][4];
    #pragma unroll
    for (int mt = 0; mt < 2; mt++) {
        const uint32_t ad = aQ + (qbase + mt * 16 + qrow) * 48 + qseg * 16;
        LDSM4(qf[mt][0], qf[mt][1], qf[mt][2], qf[mt][3], ad);
    }

    const int krow = (lane & 7) + ((lane >> 4) & 1) * 8;
    const int kseg = (lane >> 3) & 1;
    const uint32_t aKl = aK + krow * 48 + kseg * 16;

    const int vd = ((lane >> 4) & 1) * 8 + (lane & 7);
    const uint32_t aVd = aV + vd * 1024;
    const int vsw = (vd & 7) << 4;
    const int vm = ((lane >> 3) & 1) << 4;
    const int l4 = lane & 15;
    const uint32_t aV2 = aV + (16 + (l4 & 7)) * 1024;
    const int vsw2 = (l4 & 7) << 4;
    const int vm2 = ((l4 >> 3) & 1) << 4;

    float O[2][3][4] = {};   // [mt][dims0-7, dims8-15, rowsum tile]

    // -------- explicit double-buffered fragments --------
    uint32_t kf[2][4], vf[2][4], vf2[2][2];
    LDSM4(kf[0][0], kf[0][1], kf[0][2], kf[0][3], aKl);
    LDSM4(vf[0][0], vf[0][1], vf[0][2], vf[0][3], aVd + (uint32_t)(vm ^ vsw));
    LDSM2(vf2[0][0], vf2[0][1], aV2 + (uint32_t)(vm2 ^ vsw2));

    #pragma unroll 2
    for (int nb = 0; nb < 32; nb++) {
        const int cur = nb & 1, nxt = cur ^ 1;
        if (nb < 31) {
            LDSM4(kf[nxt][0], kf[nxt][1], kf[nxt][2], kf[nxt][3], aKl + (nb + 1) * 768);
            LDSM4(vf[nxt][0], vf[nxt][1], vf[nxt][2], vf[nxt][3],
                  aVd + (uint32_t)(((nb + 1) * 32 + vm) ^ vsw));
            LDSM2(vf2[nxt][0], vf2[nxt][1], aV2 + (uint32_t)(((nb + 1) * 32 + vm2) ^ vsw2));
        }
        #pragma unroll
        for (int mt = 0; mt < 2; mt++) {
            uint32_t s0[2] = {0u, 0u}, s1[2] = {0u, 0u};
            MMA_F16C(s0, qf[mt], kf[cur][0], kf[cur][1]);   // keys 0-7
            MMA_F16C(s1, qf[mt], kf[cur][2], kf[cur][3]);   // keys 8-15
            uint32_t A[4];
            A[0] = ex2h2(s0[0]);
            A[1] = ex2h2(s0[1]);
            A[2] = ex2h2(s1[0]);
            A[3] = ex2h2(s1[1]);
            MMA_F16(O[mt][0], A, vf[cur][0], vf[cur][1]);
            MMA_F16(O[mt][1], A, vf[cur][2], vf[cur][3]);
            MMA_F16(O[mt][2], A, vf2[cur][0], vf2[cur][1]);  // rowsum at tile col 16
        }
    }

    // rowsum -> normalize (c0 = row g, c2 = row g+8 of quad-leader lanes)
    #pragma unroll
    for (int mt = 0; mt < 2; mt++) {
        const float sg = __shfl_sync(0xFFFFFFFFu, O[mt][2][0], lane & ~3);
        const float sh = __shfl_sync(0xFFFFFFFFu, O[mt][2][2], lane & ~3);
        const float ig = 1.0f / sg, ih = 1.0f / sh;
        #pragma unroll
        for (int vt = 0; vt < 2; vt++) {
            O[mt][vt][0] *= ig; O[mt][vt][1] *= ig;
            O[mt][vt][2] *= ih; O[mt][vt][3] *= ih;
        }
    }

    __syncthreads();   // all warps done reading Qs/Ks

    #pragma unroll
    for (int mt = 0; mt < 2; mt++)
        #pragma unroll
        for (int vt = 0; vt < 2; vt++) {
            const int r0 = qbase + mt * 16 + (lane >> 2);
            const int cb = (vt * 8 + (lane & 3) * 2) * 4;
            *(float2*)(Os + r0 * 80 + cb)       = make_float2(O[mt][vt][0], O[mt][vt][1]);
            *(float2*)(Os + (r0 + 8) * 80 + cb) = make_float2(O[mt][vt][2], O[mt][vt][3]);
        }
    __syncthreads();

    // ---------------- epilogue: 1 query/thread; LePE from gmem (L2-hot) ----------------
    {
        const int t = tid, y = t >> 3, x = t & 7;
        float o[16];
        #pragma unroll
        for (int c = 0; c < 4; c++) {
            const float4 f = *(const float4*)(Os + t * 80 + c * 16);
            o[c * 4] = f.x; o[c * 4 + 1] = f.y; o[c * 4 + 2] = f.z; o[c * 4 + 3] = f.w;
        }
        #pragma unroll
        for (int d = 0; d < 16; d++) o[d] += bc[d];

        #pragma unroll
        for (int dy = -1; dy <= 1; dy++) {
            const int yy = y + dy;
            if ((unsigned)yy >= 64u) continue;
            #pragma unroll
            for (int dx = -1; dx <= 1; dx++) {
                const int xx = x + dx;
                if ((unsigned)xx >= 8u) continue;
                const int nn = (yy << 6) + (wx << 3) + xx;
                const float4* vrow = (const float4*)(vb + (size_t)nn * 64);
                const int widx = (dy + 1) * 3 + (dx + 1);
                #pragma unroll
                for (int c = 0; c < 4; c++) {
                    const float4 v = vrow[c];
                    o[c * 4]     += wc[c * 4][widx] * v.x;
                    o[c * 4 + 1] += wc[c * 4 + 1][widx] * v.y;
                    o[c * 4 + 2] += wc[c * 4 + 2][widx] * v.z;
                    o[c * 4 + 3] += wc[c * 4 + 3][widx] * v.w;
                }
            }
        }
        const int n = (y << 6) + (wx << 3) + x;
        float4* dst = (float4*)(out + ((size_t)b * 4096 + n) * 64 + h * 16);
        #pragma unroll
        for (int c = 0; c < 4; c++)
            dst[c] = make_float4(o[c * 4], o[c * 4 + 1], o[c * 4 + 2], o[c * 4 + 3]);
    }
}

extern "C" void kernel_launch(void* const* d_in, const int* in_sizes, int n_in,
                              void* d_out, int out_size) {
    const float* qkv = (const float*)d_in[0];
    const float* wconv = (const float*)d_in[1];
    const float* bconv = (const float*)d_in[2];
    float* out = (float*)d_out;
    const int smem_bytes = 73728;
    cudaFuncSetAttribute(cssa_mma, cudaFuncAttributeMaxDynamicSharedMemorySize, smem_bytes);
    cssa_mma<<<1024, 512, smem_bytes>>>(qkv, wconv, bconv, out);
}

// round 12
// speedup vs baseline: 1.2624x; 1.2446x over previous
#include <cuda_runtime.h>
#include <cuda_fp16.h>
#include <cstdint>

#define QSC 0.36067376022224085f   // 0.25 * log2(e)

__device__ __forceinline__ uint32_t s2u(const void* p) {
    uint32_t a;
    asm("{ .reg .u64 t; cvta.to.shared.u64 t, %1; cvt.u32.u64 %0, t; }" : "=r"(a) : "l"(p));
    return a;
}
__device__ __forceinline__ uint32_t pkh2(float hi, float lo) {
    uint32_t d;
    asm("cvt.rn.f16x2.f32 %0, %1, %2;" : "=r"(d) : "f"(hi), "f"(lo));
    return d;
}
__device__ __forceinline__ uint32_t ex2h2(uint32_t x) {
    uint32_t d;
    asm("ex2.approx.f16x2 %0, %1;" : "=r"(d) : "r"(x));
    return d;
}
#define LDSM4(r0, r1, r2, r3, a) \
    asm volatile("ldmatrix.sync.aligned.m8n8.x4.shared.b16 {%0,%1,%2,%3}, [%4];" \
        : "=r"(r0), "=r"(r1), "=r"(r2), "=r"(r3) : "r"(a))
#define LDSM2(r0, r1, a) \
    asm volatile("ldmatrix.sync.aligned.m8n8.x2.shared.b16 {%0,%1}, [%2];" \
        : "=r"(r0), "=r"(r1) : "r"(a))
// m16n8k8 f16 MMA, f32 accum: A = 2 regs (one k8 half), B = 1 reg
#define MMA_K8(c, a0, a1, b0) \
    asm volatile("mma.sync.aligned.m16n8k8.row.col.f32.f16.f16.f32 " \
        "{%0,%1,%2,%3},{%4,%5},{%6},{%0,%1,%2,%3};" \
        : "+f"((c)[0]), "+f"((c)[1]), "+f"((c)[2]), "+f"((c)[3]) \
        : "r"(a0), "r"(a1), "r"(b0))
#define MMA_F16C(c, a, b0, b1) \
    asm volatile("mma.sync.aligned.m16n8k16.row.col.f16.f16.f16.f16 " \
        "{%0,%1},{%2,%3,%4,%5},{%6,%7},{%0,%1};" \
        : "+r"((c)[0]), "+r"((c)[1]) \
        : "r"((a)[0]), "r"((a)[1]), "r"((a)[2]), "r"((a)[3]), "r"(b0), "r"(b1))

// CTA = one (window, head): 512 q x 512 k, 512 threads, 16 warps, 32 q/warp.
// smem (dynamic, 114688 B):
//  Qs @ 0     : 512 rows x 48B stride, f16 [16 dims]             (24 KB)
//  Ks @ 24576 : same                                              (24 KB)
//  Vh @ 49152 : f16 transposed [24 dims][512 keys], swizzled;
//               dim16 = 1.0 (rowsum), dims17-23 = 0               (24 KB)
//  Vf @ 73728 : f32 [512][16], 80B padded rows                    (40 KB)
//  Os @ 0     : overlay on Qs/Ks after mainloop, 512 x 80B        (40 KB)

extern "C" __global__ void __launch_bounds__(512, 1)
cssa_mma(const float* __restrict__ qkv, const float* __restrict__ wconv,
         const float* __restrict__ bconv, float* __restrict__ out)
{
    extern __shared__ char sm[];
    char* Qs = sm;
    char* Ks = sm + 24576;
    char* Vh = sm + 49152;
    char* Vf = sm + 73728;
    char* Os = sm;
    __shared__ float wc[16][9];
    __shared__ float bc[16];

    const int blk = blockIdx.x;
    const int h = blk & 3, wi = blk >> 2, b = wi >> 3, wx = wi & 7;
    const int tid = threadIdx.x, lane = tid & 31, w = tid >> 5;

    const size_t bs = (size_t)4096 * 64;
    const float* qb = qkv + (size_t)b * bs + h * 16;
    const float* kb = qb + (size_t)32 * bs;
    const float* vb = kb + (size_t)32 * bs;

    if (tid < 144) wc[tid / 9][tid % 9] = wconv[(h * 16 + tid / 9) * 9 + tid % 9];
    if (tid < 16)  bc[tid] = bconv[h * 16 + tid];

    // ---------------- staging: one token per thread ----------------
    {
        const int t = tid;
        const int n = ((t >> 3) << 6) + (wx << 3) + (t & 7);
        const float4* qr = (const float4*)(qb + (size_t)n * 64);
        const float4* kr = (const float4*)(kb + (size_t)n * 64);
        const float4* vr = (const float4*)(vb + (size_t)n * 64);
        uint32_t qh[8], kh[8];
        #pragma unroll
        for (int c = 0; c < 4; c++) {
            const float4 q4 = qr[c];
            qh[c * 2 + 0] = pkh2(q4.y * QSC, q4.x * QSC);
            qh[c * 2 + 1] = pkh2(q4.w * QSC, q4.z * QSC);
            const float4 k4 = kr[c];
            kh[c * 2 + 0] = pkh2(k4.y, k4.x);
            kh[c * 2 + 1] = pkh2(k4.w, k4.z);
            const float4 v4 = vr[c];
            *(float4*)(Vf + t * 80 + (c << 4)) = v4;
            const float e[4] = {v4.x, v4.y, v4.z, v4.w};
            #pragma unroll
            for (int jj = 0; jj < 4; jj++) {
                const int d = c * 4 + jj;
                *(__half*)(Vh + d * 1024 + (((t >> 3) ^ (d & 7)) << 4) + ((t & 7) << 1)) =
                    __float2half_rn(e[jj]);
            }
        }
        #pragma unroll
        for (int d = 16; d < 24; d++) {
            *(uint16_t*)(Vh + d * 1024 + (((t >> 3) ^ (d & 7)) << 4) + ((t & 7) << 1)) =
                (d == 16) ? (uint16_t)0x3C00u : (uint16_t)0u;
        }
        *(uint4*)(Qs + t * 48)      = make_uint4(qh[0], qh[1], qh[2], qh[3]);
        *(uint4*)(Qs + t * 48 + 16) = make_uint4(qh[4], qh[5], qh[6], qh[7]);
        *(uint4*)(Ks + t * 48)      = make_uint4(kh[0], kh[1], kh[2], kh[3]);
        *(uint4*)(Ks + t * 48 + 16) = make_uint4(kh[4], kh[5], kh[6], kh[7]);
    }
    __syncthreads();

    // ---------------- main loop: warp owns 32 queries (2 mt tiles) ----------------
    const int qbase = w * 32;
    const uint32_t aQ = s2u(Qs), aK = s2u(Ks), aV = s2u(Vh);

    const int qrow = (lane & 7) + ((lane >> 3) & 1) * 8;
    const int qseg = (lane >> 4) & 1;
    uint32_t qf[2][4];
    #pragma unroll
    for (int mt = 0; mt < 2; mt++) {
        const uint32_t ad = aQ + (qbase + mt * 16 + qrow) * 48 + qseg * 16;
        LDSM4(qf[mt][0], qf[mt][1], qf[mt][2], qf[mt][3], ad);
    }

    const int krow = (lane & 7) + ((lane >> 4) & 1) * 8;
    const int kseg = (lane >> 3) & 1;
    const uint32_t aKl = aK + krow * 48 + kseg * 16;

    const int vd = ((lane >> 4) & 1) * 8 + (lane & 7);
    const uint32_t aVd = aV + vd * 1024;
    const int vsw = (vd & 7) << 4;
    const int vm = ((lane >> 3) & 1) << 4;
    const int l4 = lane & 15;
    const uint32_t aV2 = aV + (16 + (l4 & 7)) * 1024;
    const int vsw2 = (l4 & 7) << 4;
    const int vm2 = ((l4 >> 3) & 1) << 4;

    float O[2][3][4] = {};   // [mt][dims0-7, dims8-15, rowsum tile]

    #pragma unroll 2
    for (int nb = 0; nb < 32; nb++) {
        uint32_t kf[4], vf[4], vf2[2];
        LDSM4(kf[0], kf[1], kf[2], kf[3], aKl + nb * 768);
        LDSM4(vf[0], vf[1], vf[2], vf[3], aVd + (uint32_t)((nb * 32 + vm) ^ vsw));
        LDSM2(vf2[0], vf2[1], aV2 + (uint32_t)((nb * 32 + vm2) ^ vsw2));

        #pragma unroll
        for (int mt = 0; mt < 2; mt++) {
            uint32_t s0[2] = {0u, 0u}, s1[2] = {0u, 0u};
            MMA_F16C(s0, qf[mt], kf[0], kf[1]);   // keys 0-7
            MMA_F16C(s1, qf[mt], kf[2], kf[3]);   // keys 8-15
            // s0 half flows immediately (independent of s1)
            const uint32_t a0 = ex2h2(s0[0]);
            const uint32_t a1 = ex2h2(s0[1]);
            MMA_K8(O[mt][0], a0, a1, vf[0]);
            MMA_K8(O[mt][1], a0, a1, vf[2]);
            MMA_K8(O[mt][2], a0, a1, vf2[0]);
            // s1 half
            const uint32_t a2 = ex2h2(s1[0]);
            const uint32_t a3 = ex2h2(s1[1]);
            MMA_K8(O[mt][0], a2, a3, vf[1]);
            MMA_K8(O[mt][1], a2, a3, vf[3]);
            MMA_K8(O[mt][2], a2, a3, vf2[1]);
        }
    }

    // rowsum -> normalize (c0 = row g, c2 = row g+8 of quad-leader lanes)
    #pragma unroll
    for (int mt = 0; mt < 2; mt++) {
        const float sg = __shfl_sync(0xFFFFFFFFu, O[mt][2][0], lane & ~3);
        const float sh = __shfl_sync(0xFFFFFFFFu, O[mt][2][2], lane & ~3);
        const float ig = 1.0f / sg, ih = 1.0f / sh;
        #pragma unroll
        for (int vt = 0; vt < 2; vt++) {
            O[mt][vt][0] *= ig; O[mt][vt][1] *= ig;
            O[mt][vt][2] *= ih; O[mt][vt][3] *= ih;
        }
    }

    __syncthreads();   // all warps done reading Qs/Ks

    #pragma unroll
    for (int mt = 0; mt < 2; mt++)
        #pragma unroll
        for (int vt = 0; vt < 2; vt++) {
            const int r0 = qbase + mt * 16 + (lane >> 2);
            const int cb = (vt * 8 + (lane & 3) * 2) * 4;
            *(float2*)(Os + r0 * 80 + cb)       = make_float2(O[mt][vt][0], O[mt][vt][1]);
            *(float2*)(Os + (r0 + 8) * 80 + cb) = make_float2(O[mt][vt][2], O[mt][vt][3]);
        }
    __syncthreads();

    // ---------------- epilogue: 1 query per thread (LePE from smem Vf) ----------------
    {
        const int t = tid, y = t >> 3, x = t & 7;
        float o[16];
        #pragma unroll
        for (int c = 0; c < 4; c++) {
            const float4 f = *(const float4*)(Os + t * 80 + c * 16);
            o[c * 4] = f.x; o[c * 4 + 1] = f.y; o[c * 4 + 2] = f.z; o[c * 4 + 3] = f.w;
        }
        #pragma unroll
        for (int d = 0; d < 16; d++) o[d] += bc[d];

        #pragma unroll
        for (int dy = -1; dy <= 1; dy++) {
            const int yy = y + dy;
            if ((unsigned)yy >= 64u) continue;
            #pragma unroll
            for (int dx = -1; dx <= 1; dx++) {
                const int xx = x + dx;
                if ((unsigned)xx >= 8u) continue;
                const char* vrow = Vf + (yy * 8 + xx) * 80;
                const int widx = (dy + 1) * 3 + (dx + 1);
                #pragma unroll
                for (int c = 0; c < 4; c++) {
                    const float4 v = *(const float4*)(vrow + c * 16);
                    o[c * 4]     += wc[c * 4][widx] * v.x;
                    o[c * 4 + 1] += wc[c * 4 + 1][widx] * v.y;
                    o[c * 4 + 2] += wc[c * 4 + 2][widx] * v.z;
                    o[c * 4 + 3] += wc[c * 4 + 3][widx] * v.w;
                }
            }
        }
        const int n = (y << 6) + (wx << 3) + x;
        float4* dst = (float4*)(out + ((size_t)b * 4096 + n) * 64 + h * 16);
        #pragma unroll
        for (int c = 0; c < 4; c++)
            dst[c] = make_float4(o[c * 4], o[c * 4 + 1], o[c * 4 + 2], o[c * 4 + 3]);
    }
}

extern "C" void kernel_launch(void* const* d_in, const int* in_sizes, int n_in,
                              void* d_out, int out_size) {
    const float* qkv = (const float*)d_in[0];
    const float* wconv = (const float*)d_in[1];
    const float* bconv = (const float*)d_in[2];
    float* out = (float*)d_out;
    const int smem_bytes = 114688;
    cudaFuncSetAttribute(cssa_mma, cudaFuncAttributeMaxDynamicSharedMemorySize, smem_bytes);
    cssa_mma<<<1024, 512, smem_bytes>>>(qkv, wconv, bconv, out);
}

// round 13
// speedup vs baseline: 1.4722x; 1.1662x over previous
#include <cuda_runtime.h>
#include <cuda_fp16.h>
#include <cstdint>

#define QSC 0.36067376022224085f   // 0.25 * log2(e)

__device__ __forceinline__ uint32_t s2u(const void* p) {
    uint32_t a;
    asm("{ .reg .u64 t; cvta.to.shared.u64 t, %1; cvt.u32.u64 %0, t; }" : "=r"(a) : "l"(p));
    return a;
}
__device__ __forceinline__ uint32_t pkh2(float hi, float lo) {
    uint32_t d;
    asm("cvt.rn.f16x2.f32 %0, %1, %2;" : "=r"(d) : "f"(hi), "f"(lo));
    return d;
}
__device__ __forceinline__ uint32_t ex2h2(uint32_t x) {
    uint32_t d;
    asm("ex2.approx.f16x2 %0, %1;" : "=r"(d) : "r"(x));
    return d;
}
#define LDSM4(r0, r1, r2, r3, a) \
    asm volatile("ldmatrix.sync.aligned.m8n8.x4.shared.b16 {%0,%1,%2,%3}, [%4];" \
        : "=r"(r0), "=r"(r1), "=r"(r2), "=r"(r3) : "r"(a))
#define LDSM2(r0, r1, a) \
    asm volatile("ldmatrix.sync.aligned.m8n8.x2.shared.b16 {%0,%1}, [%2];" \
        : "=r"(r0), "=r"(r1) : "r"(a))
#define MMA_F16(c, a, b0, b1) \
    asm volatile("mma.sync.aligned.m16n8k16.row.col.f32.f16.f16.f32 " \
        "{%0,%1,%2,%3},{%4,%5,%6,%7},{%8,%9},{%0,%1,%2,%3};" \
        : "+f"((c)[0]), "+f"((c)[1]), "+f"((c)[2]), "+f"((c)[3]) \
        : "r"((a)[0]), "r"((a)[1]), "r"((a)[2]), "r"((a)[3]), "r"(b0), "r"(b1))
#define MMA_F16C(c, a, b0, b1) \
    asm volatile("mma.sync.aligned.m16n8k16.row.col.f16.f16.f16.f16 " \
        "{%0,%1},{%2,%3,%4,%5},{%6,%7},{%0,%1};" \
        : "+r"((c)[0]), "+r"((c)[1]) \
        : "r"((a)[0]), "r"((a)[1]), "r"((a)[2]), "r"((a)[3]), "r"(b0), "r"(b1))

// CTA = one (window, head): 512 q x 512 k, 512 threads, 16 warps, 32 q/warp.
// smem (dynamic, 114688 B):
//  Qs @ 0     : 512 rows x 48B stride, f16 [16 dims]             (24 KB)
//  Ks @ 24576 : same                                              (24 KB)
//  Vh @ 49152 : f16 transposed [24 dims][512 keys], swizzled;
//               dim16 = 1.0 (rowsum), dims17-23 = 0               (24 KB)
//  Vf @ 73728 : f32 [512][16], 80B padded rows                    (40 KB)
//  Os @ 0     : overlay on Qs/Ks after mainloop, 512 x 80B        (40 KB)

extern "C" __global__ void __launch_bounds__(512, 1)
cssa_mma(const float* __restrict__ qkv, const float* __restrict__ wconv,
         const float* __restrict__ bconv, float* __restrict__ out)
{
    extern __shared__ char sm[];
    char* Qs = sm;
    char* Ks = sm + 24576;
    char* Vh = sm + 49152;
    char* Vf = sm + 73728;
    char* Os = sm;
    __shared__ float wc[16][9];
    __shared__ float bc[16];

    const int blk = blockIdx.x;
    const int h = blk & 3, wi = blk >> 2, b = wi >> 3, wx = wi & 7;
    const int tid = threadIdx.x, lane = tid & 31, w = tid >> 5;

    const size_t bs = (size_t)4096 * 64;
    const float* qb = qkv + (size_t)b * bs + h * 16;
    const float* kb = qb + (size_t)32 * bs;
    const float* vb = kb + (size_t)32 * bs;

    if (tid < 144) wc[tid / 9][tid % 9] = wconv[(h * 16 + tid / 9) * 9 + tid % 9];
    if (tid < 16)  bc[tid] = bconv[h * 16 + tid];

    // ---------------- staging: one token per thread ----------------
    {
        const int t = tid;
        const int n = ((t >> 3) << 6) + (wx << 3) + (t & 7);
        const float4* qr = (const float4*)(qb + (size_t)n * 64);
        const float4* kr = (const float4*)(kb + (size_t)n * 64);
        const float4* vr = (const float4*)(vb + (size_t)n * 64);
        uint32_t qh[8], kh[8];
        #pragma unroll
        for (int c = 0; c < 4; c++) {
            const float4 q4 = qr[c];
            qh[c * 2 + 0] = pkh2(q4.y * QSC, q4.x * QSC);
            qh[c * 2 + 1] = pkh2(q4.w * QSC, q4.z * QSC);
            const float4 k4 = kr[c];
            kh[c * 2 + 0] = pkh2(k4.y, k4.x);
            kh[c * 2 + 1] = pkh2(k4.w, k4.z);
            const float4 v4 = vr[c];
            *(float4*)(Vf + t * 80 + (c << 4)) = v4;
            const float e[4] = {v4.x, v4.y, v4.z, v4.w};
            #pragma unroll
            for (int jj = 0; jj < 4; jj++) {
                const int d = c * 4 + jj;
                *(__half*)(Vh + d * 1024 + (((t >> 3) ^ (d & 7)) << 4) + ((t & 7) << 1)) =
                    __float2half_rn(e[jj]);
            }
        }
        #pragma unroll
        for (int d = 16; d < 24; d++) {
            *(uint16_t*)(Vh + d * 1024 + (((t >> 3) ^ (d & 7)) << 4) + ((t & 7) << 1)) =
                (d == 16) ? (uint16_t)0x3C00u : (uint16_t)0u;
        }
        *(uint4*)(Qs + t * 48)      = make_uint4(qh[0], qh[1], qh[2], qh[3]);
        *(uint4*)(Qs + t * 48 + 16) = make_uint4(qh[4], qh[5], qh[6], qh[7]);
        *(uint4*)(Ks + t * 48)      = make_uint4(kh[0], kh[1], kh[2], kh[3]);
        *(uint4*)(Ks + t * 48 + 16) = make_uint4(kh[4], kh[5], kh[6], kh[7]);
    }
    __syncthreads();

    // ---------------- main loop: warp owns 32 queries (2 mt tiles) ----------------
    const int qbase = w * 32;
    const uint32_t aQ = s2u(Qs), aK = s2u(Ks), aV = s2u(Vh);

    const int qrow = (lane & 7) + ((lane >> 3) & 1) * 8;
    const int qseg = (lane >> 4) & 1;
    uint32_t qf[2][4];
    #pragma unroll
    for (int mt = 0; mt < 2; mt++) {
        const uint32_t ad = aQ + (qbase + mt * 16 + qrow) * 48 + qseg * 16;
        LDSM4(qf[mt][0], qf[mt][1], qf[mt][2], qf[mt][3], ad);
    }

    const int krow = (lane & 7) + ((lane >> 4) & 1) * 8;
    const int kseg = (lane >> 3) & 1;
    const uint32_t aKl = aK + krow * 48 + kseg * 16;

    const int vd = ((lane >> 4) & 1) * 8 + (lane & 7);
    const uint32_t aVd = aV + vd * 1024;
    const int vsw = (vd & 7) << 4;
    const int vm = ((lane >> 3) & 1) << 4;
    const int l4 = lane & 15;
    const uint32_t aV2 = aV + (16 + (l4 & 7)) * 1024;
    const int vsw2 = (l4 & 7) << 4;
    const int vm2 = ((l4 >> 3) & 1) << 4;

    float Oe[2][2][4] = {};   // even key-blocks [mt][vt]
    float Oo[2][2][4] = {};   // odd  key-blocks [mt][vt]
    float Or[2][4] = {};      // rowsum tile (single chain)

    #pragma unroll 4
    for (int nb = 0; nb < 32; nb++) {
        uint32_t kf[4], vf[4], vf2[2];
        LDSM4(kf[0], kf[1], kf[2], kf[3], aKl + nb * 768);
        LDSM4(vf[0], vf[1], vf[2], vf[3], aVd + (uint32_t)((nb * 32 + vm) ^ vsw));
        LDSM2(vf2[0], vf2[1], aV2 + (uint32_t)((nb * 32 + vm2) ^ vsw2));

        float (*O)[2][4] = (nb & 1) ? Oo : Oe;
        #pragma unroll
        for (int mt = 0; mt < 2; mt++) {
            uint32_t s0[2] = {0u, 0u}, s1[2] = {0u, 0u};
            MMA_F16C(s0, qf[mt], kf[0], kf[1]);   // keys 0-7
            MMA_F16C(s1, qf[mt], kf[2], kf[3]);   // keys 8-15
            uint32_t A[4];
            A[0] = ex2h2(s0[0]);
            A[1] = ex2h2(s0[1]);
            A[2] = ex2h2(s1[0]);
            A[3] = ex2h2(s1[1]);
            MMA_F16(O[mt][0], A, vf[0], vf[1]);
            MMA_F16(O[mt][1], A, vf[2], vf[3]);
            MMA_F16(Or[mt], A, vf2[0], vf2[1]);   // rowsum at tile col 16
        }
    }

    // combine even/odd, rowsum -> normalize
    #pragma unroll
    for (int mt = 0; mt < 2; mt++) {
        const float sg = __shfl_sync(0xFFFFFFFFu, Or[mt][0], lane & ~3);
        const float sh = __shfl_sync(0xFFFFFFFFu, Or[mt][2], lane & ~3);
        const float ig = 1.0f / sg, ih = 1.0f / sh;
        #pragma unroll
        for (int vt = 0; vt < 2; vt++) {
            Oe[mt][vt][0] = (Oe[mt][vt][0] + Oo[mt][vt][0]) * ig;
            Oe[mt][vt][1] = (Oe[mt][vt][1] + Oo[mt][vt][1]) * ig;
            Oe[mt][vt][2] = (Oe[mt][vt][2] + Oo[mt][vt][2]) * ih;
            Oe[mt][vt][3] = (Oe[mt][vt][3] + Oo[mt][vt][3]) * ih;
        }
    }

    __syncthreads();   // all warps done reading Qs/Ks

    #pragma unroll
    for (int mt = 0; mt < 2; mt++)
        #pragma unroll
        for (int vt = 0; vt < 2; vt++) {
            const int r0 = qbase + mt * 16 + (lane >> 2);
            const int cb = (vt * 8 + (lane & 3) * 2) * 4;
            *(float2*)(Os + r0 * 80 + cb)       = make_float2(Oe[mt][vt][0], Oe[mt][vt][1]);
            *(float2*)(Os + (r0 + 8) * 80 + cb) = make_float2(Oe[mt][vt][2], Oe[mt][vt][3]);
        }
    __syncthreads();

    // ---------------- epilogue: 1 query per thread (LePE from smem Vf) ----------------
    {
        const int t = tid, y = t >> 3, x = t & 7;
        float o[16];
        #pragma unroll
        for (int c = 0; c < 4; c++) {
            const float4 f = *(const float4*)(Os + t * 80 + c * 16);
            o[c * 4] = f.x; o[c * 4 + 1] = f.y; o[c * 4 + 2] = f.z; o[c * 4 + 3] = f.w;
        }
        #pragma unroll
        for (int d = 0; d < 16; d++) o[d] += bc[d];

        #pragma unroll
        for (int dy = -1; dy <= 1; dy++) {
            const int yy = y + dy;
            if ((unsigned)yy >= 64u) continue;
            #pragma unroll
            for (int dx = -1; dx <= 1; dx++) {
                const int xx = x + dx;
                if ((unsigned)xx >= 8u) continue;
                const char* vrow = Vf + (yy * 8 + xx) * 80;
                const int widx = (dy + 1) * 3 + (dx + 1);
                #pragma unroll
                for (int c = 0; c < 4; c++) {
                    const float4 v = *(const float4*)(vrow + c * 16);
                    o[c * 4]     += wc[c * 4][widx] * v.x;
                    o[c * 4 + 1] += wc[c * 4 + 1][widx] * v.y;
                    o[c * 4 + 2] += wc[c * 4 + 2][widx] * v.z;
                    o[c * 4 + 3] += wc[c * 4 + 3][widx] * v.w;
                }
            }
        }
        const int n = (y << 6) + (wx << 3) + x;
        float4* dst = (float4*)(out + ((size_t)b * 4096 + n) * 64 + h * 16);
        #pragma unroll
        for (int c = 0; c < 4; c++)
            dst[c] = make_float4(o[c * 4], o[c * 4 + 1], o[c * 4 + 2], o[c * 4 + 3]);
    }
}

extern "C" void kernel_launch(void* const* d_in, const int* in_sizes, int n_in,
                              void* d_out, int out_size) {
    const float* qkv = (const float*)d_in[0];
    const float* wconv = (const float*)d_in[1];
    const float* bconv = (const float*)d_in[2];
    float* out = (float*)d_out;
    const int smem_bytes = 114688;
    cudaFuncSetAttribute(cssa_mma, cudaFuncAttributeMaxDynamicSharedMemorySize, smem_bytes);
    cssa_mma<<<1024, 512, smem_bytes>>>(qkv, wconv, bconv, out);
}

// round 14
// speedup vs baseline: 1.5208x; 1.0330x over previous
#include <cuda_runtime.h>
#include <cuda_fp16.h>
#include <cstdint>

#define QSC 0.36067376022224085f   // 0.25 * log2(e)

__device__ __forceinline__ uint32_t s2u(const void* p) {
    uint32_t a;
    asm("{ .reg .u64 t; cvta.to.shared.u64 t, %1; cvt.u32.u64 %0, t; }" : "=r"(a) : "l"(p));
    return a;
}
__device__ __forceinline__ uint32_t pkh2(float hi, float lo) {
    uint32_t d;
    asm("cvt.rn.f16x2.f32 %0, %1, %2;" : "=r"(d) : "f"(hi), "f"(lo));
    return d;
}
__device__ __forceinline__ uint32_t ex2h2(uint32_t x) {
    uint32_t d;
    asm("ex2.approx.f16x2 %0, %1;" : "=r"(d) : "r"(x));
    return d;
}
#define LDSM4(r0, r1, r2, r3, a) \
    asm volatile("ldmatrix.sync.aligned.m8n8.x4.shared.b16 {%0,%1,%2,%3}, [%4];" \
        : "=r"(r0), "=r"(r1), "=r"(r2), "=r"(r3) : "r"(a))
#define LDSM2(r0, r1, a) \
    asm volatile("ldmatrix.sync.aligned.m8n8.x2.shared.b16 {%0,%1}, [%2];" \
        : "=r"(r0), "=r"(r1) : "r"(a))
#define MMA_F16(c, a, b0, b1) \
    asm volatile("mma.sync.aligned.m16n8k16.row.col.f32.f16.f16.f32 " \
        "{%0,%1,%2,%3},{%4,%5,%6,%7},{%8,%9},{%0,%1,%2,%3};" \
        : "+f"((c)[0]), "+f"((c)[1]), "+f"((c)[2]), "+f"((c)[3]) \
        : "r"((a)[0]), "r"((a)[1]), "r"((a)[2]), "r"((a)[3]), "r"(b0), "r"(b1))
#define MMA_F16C(c, a, b0, b1) \
    asm volatile("mma.sync.aligned.m16n8k16.row.col.f16.f16.f16.f16 " \
        "{%0,%1},{%2,%3,%4,%5},{%6,%7},{%0,%1};" \
        : "+r"((c)[0]), "+r"((c)[1]) \
        : "r"((a)[0]), "r"((a)[1]), "r"((a)[2]), "r"((a)[3]), "r"(b0), "r"(b1))

// CTA = HALF a (window, head): 256 queries, all 512 keys. grid = 2048,
// 256 threads, exactly 2 CTAs/SM (independent barrier domains for phase overlap).
// smem (dynamic, 90112 B):
//  Ks @ 0     : 512 rows x 48B stride, f16 [16 dims]             (24 KB)
//  Vh @ 24576 : f16 transposed [24 dims][512 keys], swizzled;
//               dim16 = 1.0 (rowsum), dims17-23 = 0               (24 KB)
//  Vf @ 49152 : f32 [512][16], 80B padded rows                    (40 KB)
//  Os @ 0     : overlay on Ks after mainloop, 256 x 80B           (20 KB)

extern "C" __global__ void __launch_bounds__(256, 2)
cssa_mma(const float* __restrict__ qkv, const float* __restrict__ wconv,
         const float* __restrict__ bconv, float* __restrict__ out)
{
    extern __shared__ char sm[];
    char* Ks = sm;
    char* Vh = sm + 24576;
    char* Vf = sm + 49152;
    char* Os = sm;
    __shared__ float wc[16][9];
    __shared__ float bc[16];

    const int blk = blockIdx.x;            // ((b*8+wx)*4+h)*2 + qh2
    const int qh2 = blk & 1;
    const int h   = (blk >> 1) & 3;
    const int wi  = blk >> 3;
    const int b   = wi >> 3, wx = wi & 7;
    const int tid = threadIdx.x, lane = tid & 31, w = tid >> 5;

    const size_t bs = (size_t)4096 * 64;
    const float* qb = qkv + (size_t)b * bs + h * 16;
    const float* kb = qb + (size_t)32 * bs;
    const float* vb = kb + (size_t)32 * bs;

    if (tid < 144) wc[tid / 9][tid % 9] = wconv[(h * 16 + tid / 9) * 9 + tid % 9];
    if (tid < 16)  bc[tid] = bconv[h * 16 + tid];

    // ---------------- staging: K + V full window, 2 tokens/thread ----------------
    #pragma unroll
    for (int j = 0; j < 2; j++) {
        const int t = tid + j * 256;
        const int n = ((t >> 3) << 6) + (wx << 3) + (t & 7);
        const float4* kr = (const float4*)(kb + (size_t)n * 64);
        const float4* vr = (const float4*)(vb + (size_t)n * 64);
        uint32_t kh[8];
        #pragma unroll
        for (int c = 0; c < 4; c++) {
            const float4 k4 = kr[c];
            kh[c * 2 + 0] = pkh2(k4.y, k4.x);
            kh[c * 2 + 1] = pkh2(k4.w, k4.z);
            const float4 v4 = vr[c];
            *(float4*)(Vf + t * 80 + (c << 4)) = v4;
            const float e[4] = {v4.x, v4.y, v4.z, v4.w};
            #pragma unroll
            for (int jj = 0; jj < 4; jj++) {
                const int d = c * 4 + jj;
                *(__half*)(Vh + d * 1024 + (((t >> 3) ^ (d & 7)) << 4) + ((t & 7) << 1)) =
                    __float2half_rn(e[jj]);
            }
        }
        #pragma unroll
        for (int d = 16; d < 24; d++) {
            *(uint16_t*)(Vh + d * 1024 + (((t >> 3) ^ (d & 7)) << 4) + ((t & 7) << 1)) =
                (d == 16) ? (uint16_t)0x3C00u : (uint16_t)0u;
        }
        *(uint4*)(Ks + t * 48)      = make_uint4(kh[0], kh[1], kh[2], kh[3]);
        *(uint4*)(Ks + t * 48 + 16) = make_uint4(kh[4], kh[5], kh[6], kh[7]);
    }

    // ---------------- Q A-fragments direct from gmem (2 mt tiles) ----------------
    const int qbase = w * 32;              // local base within this half
    uint32_t qf[2][4];
    {
        const int g  = lane >> 2;
        const int t2 = (lane & 3) * 2;
        #pragma unroll
        for (int mt = 0; mt < 2; mt++) {
            const int r0 = qh2 * 256 + qbase + mt * 16 + g;   // window query index
            #pragma unroll
            for (int half8 = 0; half8 < 2; half8++) {
                const int rq = r0 + half8 * 8;
                const int n  = ((rq >> 3) << 6) + (wx << 3) + (rq & 7);
                const float2 f0 = *(const float2*)(qb + (size_t)n * 64 + t2);
                const float2 f1 = *(const float2*)(qb + (size_t)n * 64 + 8 + t2);
                qf[mt][half8]     = pkh2(f0.y * QSC, f0.x * QSC);
                qf[mt][half8 + 2] = pkh2(f1.y * QSC, f1.x * QSC);
            }
        }
    }
    __syncthreads();

    // ---------------- main loop over 512 keys ----------------
    const uint32_t aK = s2u(Ks), aV = s2u(Vh);
    const int krow = (lane & 7) + ((lane >> 4) & 1) * 8;
    const int kseg = (lane >> 3) & 1;
    const uint32_t aKl = aK + krow * 48 + kseg * 16;

    const int vd = ((lane >> 4) & 1) * 8 + (lane & 7);
    const uint32_t aVd = aV + vd * 1024;
    const int vsw = (vd & 7) << 4;
    const int vm = ((lane >> 3) & 1) << 4;
    const int l4 = lane & 15;
    const uint32_t aV2 = aV + (16 + (l4 & 7)) * 1024;
    const int vsw2 = (l4 & 7) << 4;
    const int vm2 = ((l4 >> 3) & 1) << 4;

    float Oe[2][2][4] = {};   // even key-blocks [mt][vt]
    float Oo[2][2][4] = {};   // odd  key-blocks [mt][vt]
    float Or[2][4] = {};      // rowsum tile (single chain)

    #pragma unroll 4
    for (int nb = 0; nb < 32; nb++) {
        uint32_t kf[4], vf[4], vf2[2];
        LDSM4(kf[0], kf[1], kf[2], kf[3], aKl + nb * 768);
        LDSM4(vf[0], vf[1], vf[2], vf[3], aVd + (uint32_t)((nb * 32 + vm) ^ vsw));
        LDSM2(vf2[0], vf2[1], aV2 + (uint32_t)((nb * 32 + vm2) ^ vsw2));

        float (*O)[2][4] = (nb & 1) ? Oo : Oe;
        #pragma unroll
        for (int mt = 0; mt < 2; mt++) {
            uint32_t s0[2] = {0u, 0u}, s1[2] = {0u, 0u};
            MMA_F16C(s0, qf[mt], kf[0], kf[1]);   // keys 0-7
            MMA_F16C(s1, qf[mt], kf[2], kf[3]);   // keys 8-15
            uint32_t A[4];
            A[0] = ex2h2(s0[0]);
            A[1] = ex2h2(s0[1]);
            A[2] = ex2h2(s1[0]);
            A[3] = ex2h2(s1[1]);
            MMA_F16(O[mt][0], A, vf[0], vf[1]);
            MMA_F16(O[mt][1], A, vf[2], vf[3]);
            MMA_F16(Or[mt], A, vf2[0], vf2[1]);   // rowsum at tile col 16
        }
    }

    // combine even/odd, rowsum -> normalize
    #pragma unroll
    for (int mt = 0; mt < 2; mt++) {
        const float sg = __shfl_sync(0xFFFFFFFFu, Or[mt][0], lane & ~3);
        const float sh = __shfl_sync(0xFFFFFFFFu, Or[mt][2], lane & ~3);
        const float ig = 1.0f / sg, ih = 1.0f / sh;
        #pragma unroll
        for (int vt = 0; vt < 2; vt++) {
            Oe[mt][vt][0] = (Oe[mt][vt][0] + Oo[mt][vt][0]) * ig;
            Oe[mt][vt][1] = (Oe[mt][vt][1] + Oo[mt][vt][1]) * ig;
            Oe[mt][vt][2] = (Oe[mt][vt][2] + Oo[mt][vt][2]) * ih;
            Oe[mt][vt][3] = (Oe[mt][vt][3] + Oo[mt][vt][3]) * ih;
        }
    }

    __syncthreads();   // all warps done reading Ks (Os overlays it)

    #pragma unroll
    for (int mt = 0; mt < 2; mt++)
        #pragma unroll
        for (int vt = 0; vt < 2; vt++) {
            const int r0 = qbase + mt * 16 + (lane >> 2);    // local 0..255
            const int cb = (vt * 8 + (lane & 3) * 2) * 4;
            *(float2*)(Os + r0 * 80 + cb)       = make_float2(Oe[mt][vt][0], Oe[mt][vt][1]);
            *(float2*)(Os + (r0 + 8) * 80 + cb) = make_float2(Oe[mt][vt][2], Oe[mt][vt][3]);
        }
    __syncthreads();

    // ---------------- epilogue: 1 query/thread (LePE from smem Vf, full window) ----------------
    {
        const int tq = qh2 * 256 + tid;      // window query index
        const int y = tq >> 3, x = tq & 7;
        float o[16];
        #pragma unroll
        for (int c = 0; c < 4; c++) {
            const float4 f = *(const float4*)(Os + tid * 80 + c * 16);
            o[c * 4] = f.x; o[c * 4 + 1] = f.y; o[c * 4 + 2] = f.z; o[c * 4 + 3] = f.w;
        }
        #pragma unroll
        for (int d = 0; d < 16; d++) o[d] += bc[d];

        #pragma unroll
        for (int dy = -1; dy <= 1; dy++) {
            const int yy = y + dy;
            if ((unsigned)yy >= 64u) continue;
            #pragma unroll
            for (int dx = -1; dx <= 1; dx++) {
                const int xx = x + dx;
                if ((unsigned)xx >= 8u) continue;
                const char* vrow = Vf + (yy * 8 + xx) * 80;
                const int widx = (dy + 1) * 3 + (dx + 1);
                #pragma unroll
                for (int c = 0; c < 4; c++) {
                    const float4 v = *(const float4*)(vrow + c * 16);
                    o[c * 4]     += wc[c * 4][widx] * v.x;
                    o[c * 4 + 1] += wc[c * 4 + 1][widx] * v.y;
                    o[c * 4 + 2] += wc[c * 4 + 2][widx] * v.z;
                    o[c * 4 + 3] += wc[c * 4 + 3][widx] * v.w;
                }
            }
        }
        const int n = (y << 6) + (wx << 3) + x;
        float4* dst = (float4*)(out + ((size_t)b * 4096 + n) * 64 + h * 16);
        #pragma unroll
        for (int c = 0; c < 4; c++)
            dst[c] = make_float4(o[c * 4], o[c * 4 + 1], o[c * 4 + 2], o[c * 4 + 3]);
    }
}

extern "C" void kernel_launch(void* const* d_in, const int* in_sizes, int n_in,
                              void* d_out, int out_size) {
    const float* qkv = (const float*)d_in[0];
    const float* wconv = (const float*)d_in[1];
    const float* bconv = (const float*)d_in[2];
    float* out = (float*)d_out;
    const int smem_bytes = 90112;
    cudaFuncSetAttribute(cssa_mma, cudaFuncAttributeMaxDynamicSharedMemorySize, smem_bytes);
    cssa_mma<<<2048, 256, smem_bytes>>>(qkv, wconv, bconv, out);
}

// round 15
// speedup vs baseline: 1.6212x; 1.0660x over previous
#include <cuda_runtime.h>
#include <cuda_fp16.h>
#include <cstdint>

#define QSC 0.36067376022224085f   // 0.25 * log2(e)

__device__ __forceinline__ uint32_t s2u(const void* p) {
    uint32_t a;
    asm("{ .reg .u64 t; cvta.to.shared.u64 t, %1; cvt.u32.u64 %0, t; }" : "=r"(a) : "l"(p));
    return a;
}
__device__ __forceinline__ uint32_t pkh2(float hi, float lo) {
    uint32_t d;
    asm("cvt.rn.f16x2.f32 %0, %1, %2;" : "=r"(d) : "f"(hi), "f"(lo));
    return d;
}
__device__ __forceinline__ uint32_t ex2h2(uint32_t x) {
    uint32_t d;
    asm("ex2.approx.f16x2 %0, %1;" : "=r"(d) : "r"(x));
    return d;
}
#define LDSM4(r0, r1, r2, r3, a) \
    asm volatile("ldmatrix.sync.aligned.m8n8.x4.shared.b16 {%0,%1,%2,%3}, [%4];" \
        : "=r"(r0), "=r"(r1), "=r"(r2), "=r"(r3) : "r"(a))
#define MMA_F16(c, a, b0, b1) \
    asm volatile("mma.sync.aligned.m16n8k16.row.col.f32.f16.f16.f32 " \
        "{%0,%1,%2,%3},{%4,%5,%6,%7},{%8,%9},{%0,%1,%2,%3};" \
        : "+f"((c)[0]), "+f"((c)[1]), "+f"((c)[2]), "+f"((c)[3]) \
        : "r"((a)[0]), "r"((a)[1]), "r"((a)[2]), "r"((a)[3]), "r"(b0), "r"(b1))
#define MMA_F16C(c, a, b0, b1) \
    asm volatile("mma.sync.aligned.m16n8k16.row.col.f16.f16.f16.f16 " \
        "{%0,%1},{%2,%3,%4,%5},{%6,%7},{%0,%1};" \
        : "+r"((c)[0]), "+r"((c)[1]) \
        : "r"((a)[0]), "r"((a)[1]), "r"((a)[2]), "r"((a)[3]), "r"(b0), "r"(b1))

// CTA = HALF a (window, head): 256 queries, all 512 keys. grid = 2048,
// 256 threads, 2 CTAs/SM (independent barrier domains for phase overlap).
// smem (dynamic, 81920 B):
//  Ks @ 0     : 512 rows x 48B stride, f16 [16 dims]             (24 KB)
//  Vh @ 24576 : f16 transposed [16 dims][512 keys], swizzled      (16 KB)
//  Vf @ 40960 : f32 [512][16], 80B padded rows                    (40 KB)
//  Os @ 0     : overlay on Ks after mainloop, 256 x 80B           (20 KB)

extern "C" __global__ void __launch_bounds__(256, 2)
cssa_mma(const float* __restrict__ qkv, const float* __restrict__ wconv,
         const float* __restrict__ bconv, float* __restrict__ out)
{
    extern __shared__ char sm[];
    char* Ks = sm;
    char* Vh = sm + 24576;
    char* Vf = sm + 40960;
    char* Os = sm;
    __shared__ float wc[16][9];
    __shared__ float bc[16];

    const int blk = blockIdx.x;            // ((b*8+wx)*4+h)*2 + qh2
    const int qh2 = blk & 1;
    const int h   = (blk >> 1) & 3;
    const int wi  = blk >> 3;
    const int b   = wi >> 3, wx = wi & 7;
    const int tid = threadIdx.x, lane = tid & 31, w = tid >> 5;

    const size_t bs = (size_t)4096 * 64;
    const float* qb = qkv + (size_t)b * bs + h * 16;
    const float* kb = qb + (size_t)32 * bs;
    const float* vb = kb + (size_t)32 * bs;

    if (tid < 144) wc[tid / 9][tid % 9] = wconv[(h * 16 + tid / 9) * 9 + tid % 9];
    if (tid < 16)  bc[tid] = bconv[h * 16 + tid];

    // ---------------- staging: K + V full window, 2 tokens/thread ----------------
    #pragma unroll
    for (int j = 0; j < 2; j++) {
        const int t = tid + j * 256;
        const int n = ((t >> 3) << 6) + (wx << 3) + (t & 7);
        const float4* kr = (const float4*)(kb + (size_t)n * 64);
        const float4* vr = (const float4*)(vb + (size_t)n * 64);
        uint32_t kh[8];
        #pragma unroll
        for (int c = 0; c < 4; c++) {
            const float4 k4 = kr[c];
            kh[c * 2 + 0] = pkh2(k4.y, k4.x);
            kh[c * 2 + 1] = pkh2(k4.w, k4.z);
            const float4 v4 = vr[c];
            *(float4*)(Vf + t * 80 + (c << 4)) = v4;
            const float e[4] = {v4.x, v4.y, v4.z, v4.w};
            #pragma unroll
            for (int jj = 0; jj < 4; jj++) {
                const int d = c * 4 + jj;
                *(__half*)(Vh + d * 1024 + (((t >> 3) ^ (d & 7)) << 4) + ((t & 7) << 1)) =
                    __float2half_rn(e[jj]);
            }
        }
        *(uint4*)(Ks + t * 48)      = make_uint4(kh[0], kh[1], kh[2], kh[3]);
        *(uint4*)(Ks + t * 48 + 16) = make_uint4(kh[4], kh[5], kh[6], kh[7]);
    }

    // ---------------- Q A-fragments direct from gmem (2 mt tiles) ----------------
    const int qbase = w * 32;              // local base within this half
    uint32_t qf[2][4];
    {
        const int g  = lane >> 2;
        const int t2 = (lane & 3) * 2;
        #pragma unroll
        for (int mt = 0; mt < 2; mt++) {
            const int r0 = qh2 * 256 + qbase + mt * 16 + g;   // window query index
            #pragma unroll
            for (int half8 = 0; half8 < 2; half8++) {
                const int rq = r0 + half8 * 8;
                const int n  = ((rq >> 3) << 6) + (wx << 3) + (rq & 7);
                const float2 f0 = *(const float2*)(qb + (size_t)n * 64 + t2);
                const float2 f1 = *(const float2*)(qb + (size_t)n * 64 + 8 + t2);
                qf[mt][half8]     = pkh2(f0.y * QSC, f0.x * QSC);
                qf[mt][half8 + 2] = pkh2(f1.y * QSC, f1.x * QSC);
            }
        }
    }
    __syncthreads();

    // ---------------- main loop over 512 keys ----------------
    const uint32_t aK = s2u(Ks), aV = s2u(Vh);
    const int krow = (lane & 7) + ((lane >> 4) & 1) * 8;
    const int kseg = (lane >> 3) & 1;
    const uint32_t aKl = aK + krow * 48 + kseg * 16;

    const int vd = ((lane >> 4) & 1) * 8 + (lane & 7);
    const uint32_t aVd = aV + vd * 1024;
    const int vsw = (vd & 7) << 4;
    const int vm = ((lane >> 3) & 1) << 4;

    // rowsum ones-column B-fragment is constant: col(n) = lane>>2; 1.0 only at tile col 0
    const uint32_t vf2c = (lane < 4) ? 0x3C003C00u : 0u;

    float Oe[2][2][4] = {};   // even key-blocks [mt][vt]
    float Oo[2][2][4] = {};   // odd  key-blocks [mt][vt]
    float Or[2][4] = {};      // rowsum tile (single chain)

    #pragma unroll 4
    for (int nb = 0; nb < 32; nb++) {
        uint32_t kf[4], vf[4];
        LDSM4(kf[0], kf[1], kf[2], kf[3], aKl + nb * 768);
        LDSM4(vf[0], vf[1], vf[2], vf[3], aVd + (uint32_t)((nb * 32 + vm) ^ vsw));

        float (*O)[2][4] = (nb & 1) ? Oo : Oe;
        #pragma unroll
        for (int mt = 0; mt < 2; mt++) {
            uint32_t s0[2] = {0u, 0u}, s1[2] = {0u, 0u};
            MMA_F16C(s0, qf[mt], kf[0], kf[1]);   // keys 0-7
            MMA_F16C(s1, qf[mt], kf[2], kf[3]);   // keys 8-15
            uint32_t A[4];
            A[0] = ex2h2(s0[0]);
            A[1] = ex2h2(s0[1]);
            A[2] = ex2h2(s1[0]);
            A[3] = ex2h2(s1[1]);
            MMA_F16(O[mt][0], A, vf[0], vf[1]);
            MMA_F16(O[mt][1], A, vf[2], vf[3]);
            MMA_F16(Or[mt], A, vf2c, vf2c);       // rowsum via constant ones-col frag
        }
    }

    // combine even/odd, rowsum -> normalize
    #pragma unroll
    for (int mt = 0; mt < 2; mt++) {
        const float sg = __shfl_sync(0xFFFFFFFFu, Or[mt][0], lane & ~3);
        const float sh = __shfl_sync(0xFFFFFFFFu, Or[mt][2], lane & ~3);
        const float ig = 1.0f / sg, ih = 1.0f / sh;
        #pragma unroll
        for (int vt = 0; vt < 2; vt++) {
            Oe[mt][vt][0] = (Oe[mt][vt][0] + Oo[mt][vt][0]) * ig;
            Oe[mt][vt][1] = (Oe[mt][vt][1] + Oo[mt][vt][1]) * ig;
            Oe[mt][vt][2] = (Oe[mt][vt][2] + Oo[mt][vt][2]) * ih;
            Oe[mt][vt][3] = (Oe[mt][vt][3] + Oo[mt][vt][3]) * ih;
        }
    }

    __syncthreads();   // all warps done reading Ks (Os overlays it)

    #pragma unroll
    for (int mt = 0; mt < 2; mt++)
        #pragma unroll
        for (int vt = 0; vt < 2; vt++) {
            const int r0 = qbase + mt * 16 + (lane >> 2);    // local 0..255
            const int cb = (vt * 8 + (lane & 3) * 2) * 4;
            *(float2*)(Os + r0 * 80 + cb)       = make_float2(Oe[mt][vt][0], Oe[mt][vt][1]);
            *(float2*)(Os + (r0 + 8) * 80 + cb) = make_float2(Oe[mt][vt][2], Oe[mt][vt][3]);
        }
    __syncthreads();

    // ---------------- epilogue: 1 query/thread (LePE from smem Vf, full window) ----------------
    {
        const int tq = qh2 * 256 + tid;      // window query index
        const int y = tq >> 3, x = tq & 7;
        float o[16];
        #pragma unroll
        for (int c = 0; c < 4; c++) {
            const float4 f = *(const float4*)(Os + tid * 80 + c * 16);
            o[c * 4] = f.x; o[c * 4 + 1] = f.y; o[c * 4 + 2] = f.z; o[c * 4 + 3] = f.w;
        }
        #pragma unroll
        for (int d = 0; d < 16; d++) o[d] += bc[d];

        #pragma unroll
        for (int dy = -1; dy <= 1; dy++) {
            const int yy = y + dy;
            if ((unsigned)yy >= 64u) continue;
            #pragma unroll
            for (int dx = -1; dx <= 1; dx++) {
                const int xx = x + dx;
                if ((unsigned)xx >= 8u) continue;
                const char* vrow = Vf + (yy * 8 + xx) * 80;
                const int widx = (dy + 1) * 3 + (dx + 1);
                #pragma unroll
                for (int c = 0; c < 4; c++) {
                    const float4 v = *(const float4*)(vrow + c * 16);
                    o[c * 4]     += wc[c * 4][widx] * v.x;
                    o[c * 4 + 1] += wc[c * 4 + 1][widx] * v.y;
                    o[c * 4 + 2] += wc[c * 4 + 2][widx] * v.z;
                    o[c * 4 + 3] += wc[c * 4 + 3][widx] * v.w;
                }
            }
        }
        const int n = (y << 6) + (wx << 3) + x;
        float4* dst = (float4*)(out + ((size_t)b * 4096 + n) * 64 + h * 16);
        #pragma unroll
        for (int c = 0; c < 4; c++)
            dst[c] = make_float4(o[c * 4], o[c * 4 + 1], o[c * 4 + 2], o[c * 4 + 3]);
    }
}

extern "C" void kernel_launch(void* const* d_in, const int* in_sizes, int n_in,
                              void* d_out, int out_size) {
    const float* qkv = (const float*)d_in[0];
    const float* wconv = (const float*)d_in[1];
    const float* bconv = (const float*)d_in[2];
    float* out = (float*)d_out;
    const int smem_bytes = 81920;
    cudaFuncSetAttribute(cssa_mma, cudaFuncAttributeMaxDynamicSharedMemorySize, smem_bytes);
    cssa_mma<<<2048, 256, smem_bytes>>>(qkv, wconv, bconv, out);
}

// round 16
// speedup vs baseline: 2.0350x; 1.2553x over previous
#include <cuda_runtime.h>
#include <cuda_fp16.h>
#include <cstdint>

#define QSC 0.36067376022224085f   // 0.25 * log2(e)

__device__ __forceinline__ uint32_t s2u(const void* p) {
    uint32_t a;
    asm("{ .reg .u64 t; cvta.to.shared.u64 t, %1; cvt.u32.u64 %0, t; }" : "=r"(a) : "l"(p));
    return a;
}
__device__ __forceinline__ uint32_t pkh2(float hi, float lo) {
    uint32_t d;
    asm("cvt.rn.f16x2.f32 %0, %1, %2;" : "=r"(d) : "f"(hi), "f"(lo));
    return d;
}
__device__ __forceinline__ uint32_t ex2h2(uint32_t x) {
    uint32_t d;
    asm("ex2.approx.f16x2 %0, %1;" : "=r"(d) : "r"(x));
    return d;
}
#define LDSM4(r0, r1, r2, r3, a) \
    asm volatile("ldmatrix.sync.aligned.m8n8.x4.shared.b16 {%0,%1,%2,%3}, [%4];" \
        : "=r"(r0), "=r"(r1), "=r"(r2), "=r"(r3) : "r"(a))
#define MMA_F16(c, a, b0, b1) \
    asm volatile("mma.sync.aligned.m16n8k16.row.col.f32.f16.f16.f32 " \
        "{%0,%1,%2,%3},{%4,%5,%6,%7},{%8,%9},{%0,%1,%2,%3};" \
        : "+f"((c)[0]), "+f"((c)[1]), "+f"((c)[2]), "+f"((c)[3]) \
        : "r"((a)[0]), "r"((a)[1]), "r"((a)[2]), "r"((a)[3]), "r"(b0), "r"(b1))
#define MMA_F16C(c, a, b0, b1) \
    asm volatile("mma.sync.aligned.m16n8k16.row.col.f16.f16.f16.f16 " \
        "{%0,%1},{%2,%3,%4,%5},{%6,%7},{%0,%1};" \
        : "+r"((c)[0]), "+r"((c)[1]) \
        : "r"((a)[0]), "r"((a)[1]), "r"((a)[2]), "r"((a)[3]), "r"(b0), "r"(b1))

// CTA = one (window, head): 512 q x 512 k, 256 threads, 8 warps x 64 queries.
// grid = 1024, 2 CTAs/SM (independent barrier domains).
// smem (dynamic, 81920 B):
//  Ks @ 0     : 512 rows x 48B stride, f16 [16 dims]             (24 KB)
//  Vh @ 24576 : f16 transposed [16 dims][512 keys], swizzled      (16 KB)
//  Vf @ 40960 : f32 [512][16], 80B padded rows                    (40 KB)
//  Os @ 0     : overlay on Ks+Vh after mainloop, 512 x 80B        (40 KB)

extern "C" __global__ void __launch_bounds__(256, 2)
cssa_mma(const float* __restrict__ qkv, const float* __restrict__ wconv,
         const float* __restrict__ bconv, float* __restrict__ out)
{
    extern __shared__ char sm[];
    char* Ks = sm;
    char* Vh = sm + 24576;
    char* Vf = sm + 40960;
    char* Os = sm;
    __shared__ float wc[16][9];
    __shared__ float bc[16];

    const int blk = blockIdx.x;
    const int h = blk & 3, wi = blk >> 2, b = wi >> 3, wx = wi & 7;
    const int tid = threadIdx.x, lane = tid & 31, w = tid >> 5;

    const size_t bs = (size_t)4096 * 64;
    const float* qb = qkv + (size_t)b * bs + h * 16;
    const float* kb = qb + (size_t)32 * bs;
    const float* vb = kb + (size_t)32 * bs;

    if (tid < 144) wc[tid / 9][tid % 9] = wconv[(h * 16 + tid / 9) * 9 + tid % 9];
    if (tid < 16)  bc[tid] = bconv[h * 16 + tid];

    // ---------------- staging: K + V full window, 2 tokens/thread ----------------
    #pragma unroll
    for (int j = 0; j < 2; j++) {
        const int t = tid + j * 256;
        const int n = ((t >> 3) << 6) + (wx << 3) + (t & 7);
        const float4* kr = (const float4*)(kb + (size_t)n * 64);
        const float4* vr = (const float4*)(vb + (size_t)n * 64);
        uint32_t kh[8];
        #pragma unroll
        for (int c = 0; c < 4; c++) {
            const float4 k4 = kr[c];
            kh[c * 2 + 0] = pkh2(k4.y, k4.x);
            kh[c * 2 + 1] = pkh2(k4.w, k4.z);
            const float4 v4 = vr[c];
            *(float4*)(Vf + t * 80 + (c << 4)) = v4;
            const float e[4] = {v4.x, v4.y, v4.z, v4.w};
            #pragma unroll
            for (int jj = 0; jj < 4; jj++) {
                const int d = c * 4 + jj;
                *(__half*)(Vh + d * 1024 + (((t >> 3) ^ (d & 7)) << 4) + ((t & 7) << 1)) =
                    __float2half_rn(e[jj]);
            }
        }
        *(uint4*)(Ks + t * 48)      = make_uint4(kh[0], kh[1], kh[2], kh[3]);
        *(uint4*)(Ks + t * 48 + 16) = make_uint4(kh[4], kh[5], kh[6], kh[7]);
    }

    // ---------------- Q A-fragments direct from gmem (4 mt tiles) ----------------
    const int qbase = w * 64;
    uint32_t qf[4][4];
    {
        const int g  = lane >> 2;
        const int t2 = (lane & 3) * 2;
        #pragma unroll
        for (int mt = 0; mt < 4; mt++) {
            const int r0 = qbase + mt * 16 + g;
            #pragma unroll
            for (int half8 = 0; half8 < 2; half8++) {
                const int rq = r0 + half8 * 8;
                const int n  = ((rq >> 3) << 6) + (wx << 3) + (rq & 7);
                const float2 f0 = *(const float2*)(qb + (size_t)n * 64 + t2);
                const float2 f1 = *(const float2*)(qb + (size_t)n * 64 + 8 + t2);
                qf[mt][half8]     = pkh2(f0.y * QSC, f0.x * QSC);
                qf[mt][half8 + 2] = pkh2(f1.y * QSC, f1.x * QSC);
            }
        }
    }
    __syncthreads();

    // ---------------- main loop over 512 keys ----------------
    const uint32_t aK = s2u(Ks), aV = s2u(Vh);
    const int krow = (lane & 7) + ((lane >> 4) & 1) * 8;
    const int kseg = (lane >> 3) & 1;
    const uint32_t aKl = aK + krow * 48 + kseg * 16;

    const int vd = ((lane >> 4) & 1) * 8 + (lane & 7);
    const uint32_t aVd = aV + vd * 1024;
    const int vsw = (vd & 7) << 4;
    const int vm = ((lane >> 3) & 1) << 4;

    // rowsum ones-column B-fragment is constant
    const uint32_t vf2c = (lane < 4) ? 0x3C003C00u : 0u;

    float O[4][2][4] = {};   // [mt][dims0-7 | dims8-15]
    float Or[4][4] = {};     // rowsum tiles

    #pragma unroll 2
    for (int nb = 0; nb < 32; nb++) {
        uint32_t kf[4], vf[4];
        LDSM4(kf[0], kf[1], kf[2], kf[3], aKl + nb * 768);
        LDSM4(vf[0], vf[1], vf[2], vf[3], aVd + (uint32_t)((nb * 32 + vm) ^ vsw));

        #pragma unroll
        for (int mt = 0; mt < 4; mt++) {
            uint32_t s0[2] = {0u, 0u}, s1[2] = {0u, 0u};
            MMA_F16C(s0, qf[mt], kf[0], kf[1]);   // keys 0-7
            MMA_F16C(s1, qf[mt], kf[2], kf[3]);   // keys 8-15
            uint32_t A[4];
            A[0] = ex2h2(s0[0]);
            A[1] = ex2h2(s0[1]);
            A[2] = ex2h2(s1[0]);
            A[3] = ex2h2(s1[1]);
            MMA_F16(O[mt][0], A, vf[0], vf[1]);
            MMA_F16(O[mt][1], A, vf[2], vf[3]);
            MMA_F16(Or[mt], A, vf2c, vf2c);       // rowsum via constant ones-col frag
        }
    }

    // rowsum -> normalize
    #pragma unroll
    for (int mt = 0; mt < 4; mt++) {
        const float sg = __shfl_sync(0xFFFFFFFFu, Or[mt][0], lane & ~3);
        const float sh = __shfl_sync(0xFFFFFFFFu, Or[mt][2], lane & ~3);
        const float ig = 1.0f / sg, ih = 1.0f / sh;
        #pragma unroll
        for (int vt = 0; vt < 2; vt++) {
            O[mt][vt][0] *= ig; O[mt][vt][1] *= ig;
            O[mt][vt][2] *= ih; O[mt][vt][3] *= ih;
        }
    }

    __syncthreads();   // all warps done reading Ks/Vh (Os overlays them)

    #pragma unroll
    for (int mt = 0; mt < 4; mt++)
        #pragma unroll
        for (int vt = 0; vt < 2; vt++) {
            const int r0 = qbase + mt * 16 + (lane >> 2);
            const int cb = (vt * 8 + (lane & 3) * 2) * 4;
            *(float2*)(Os + r0 * 80 + cb)       = make_float2(O[mt][vt][0], O[mt][vt][1]);
            *(float2*)(Os + (r0 + 8) * 80 + cb) = make_float2(O[mt][vt][2], O[mt][vt][3]);
        }
    __syncthreads();

    // ---------------- epilogue: 2 queries/thread (LePE from smem Vf) ----------------
    #pragma unroll
    for (int j = 0; j < 2; j++) {
        const int t = tid + j * 256, y = t >> 3, x = t & 7;
        float o[16];
        #pragma unroll
        for (int c = 0; c < 4; c++) {
            const float4 f = *(const float4*)(Os + t * 80 + c * 16);
            o[c * 4] = f.x; o[c * 4 + 1] = f.y; o[c * 4 + 2] = f.z; o[c * 4 + 3] = f.w;
        }
        #pragma unroll
        for (int d = 0; d < 16; d++) o[d] += bc[d];

        #pragma unroll
        for (int dy = -1; dy <= 1; dy++) {
            const int yy = y + dy;
            if ((unsigned)yy >= 64u) continue;
            #pragma unroll
            for (int dx = -1; dx <= 1; dx++) {
                const int xx = x + dx;
                if ((unsigned)xx >= 8u) continue;
                const char* vrow = Vf + (yy * 8 + xx) * 80;
                const int widx = (dy + 1) * 3 + (dx + 1);
                #pragma unroll
                for (int c = 0; c < 4; c++) {
                    const float4 v = *(const float4*)(vrow + c * 16);
                    o[c * 4]     += wc[c * 4][widx] * v.x;
                    o[c * 4 + 1] += wc[c * 4 + 1][widx] * v.y;
                    o[c * 4 + 2] += wc[c * 4 + 2][widx] * v.z;
                    o[c * 4 + 3] += wc[c * 4 + 3][widx] * v.w;
                }
            }
        }
        const int n = (y << 6) + (wx << 3) + x;
        float4* dst = (float4*)(out + ((size_t)b * 4096 + n) * 64 + h * 16);
        #pragma unroll
        for (int c = 0; c < 4; c++)
            dst[c] = make_float4(o[c * 4], o[c * 4 + 1], o[c * 4 + 2], o[c * 4 + 3]);
    }
}

extern "C" void kernel_launch(void* const* d_in, const int* in_sizes, int n_in,
                              void* d_out, int out_size) {
    const float* qkv = (const float*)d_in[0];
    const float* wconv = (const float*)d_in[1];
    const float* bconv = (const float*)d_in[2];
    float* out = (float*)d_out;
    const int smem_bytes = 81920;
    cudaFuncSetAttribute(cssa_mma, cudaFuncAttributeMaxDynamicSharedMemorySize, smem_bytes);
    cssa_mma<<<1024, 256, smem_bytes>>>(qkv, wconv, bconv, out);
}